// round 10
// baseline (speedup 1.0000x reference)
#include <cuda_runtime.h>
#include <cuda_bf16.h>
#include <math.h>
#include <stdint.h>

#define T_STEPS 4096
#define HS 512
#define INSZ 2048
#define MBK 100
#define NCTA 128
#define NTHR 512

// ---------------- device scratch (allocations are forbidden) ----------------
__device__ float g_pre_rha[T_STEPS * HS];
__device__ float g_pre_rhm[T_STEPS * HS];
__device__ float g_pre_ca [T_STEPS * HS];
__device__ float g_pre_cm [T_STEPS * HS];
__device__ float g_pre_wpa[T_STEPS * MBK];
__device__ float g_pre_wpm[T_STEPS * MBK];
__device__ float g_state[3 * HS];          // [ha(512) | hm(512) | h(512)]
__device__ float g_r[HS];
// logit accumulators, double buffered: [0..99]=ar, [100..102]=aw,
// [103..202]=aw_a(ha part), [203..302]=aw_m(hm part)
__device__ float g_acc[2][320];
__device__ unsigned int g_bar;

__device__ __forceinline__ float warpsum(float v) {
#pragma unroll
    for (int o = 16; o; o >>= 1) v += __shfl_xor_sync(0xFFFFFFFFu, v, o);
    return v;
}

// ---------------- single-counter grid barrier, split arrive/wait ----------------
__device__ __forceinline__ void gbar_arrive() {
    __syncthreads();
    if (threadIdx.x == 0) {
        __threadfence();
        atomicAdd(&g_bar, 1u);
    }
}
__device__ __forceinline__ void gbar_wait(unsigned int target) {
    if (threadIdx.x == 0) {
        int spins = 0;
        while (*(volatile unsigned int*)&g_bar < target) {
            if (++spins > 8) __nanosleep(40);
        }
        __threadfence();
    }
    __syncthreads();
}

__global__ void reset_kernel() {
    int i = threadIdx.x;
    if (i == 0) g_bar = 0u;
    float* a = &g_acc[0][0];
    for (int j = i; j < 2 * 320; j += blockDim.x) a[j] = 0.f;
}

// =====================================================================
// Precompute GEMMs: C[4096,N] = X @ W[rowOff:+2048, :N] + bias (6 jobs in z)
// =====================================================================
__global__ __launch_bounds__(256)
void gemm6_kernel(const float* __restrict__ Xa, const float* __restrict__ Xm,
                  const float* __restrict__ W_rha, const float* __restrict__ b_rha,
                  const float* __restrict__ W_rhm, const float* __restrict__ b_rhm,
                  const float* __restrict__ W_ca,  const float* __restrict__ b_ca,
                  const float* __restrict__ W_cm,  const float* __restrict__ b_cm,
                  const float* __restrict__ W_wpa, const float* __restrict__ b_wpa,
                  const float* __restrict__ W_wpm, const float* __restrict__ b_wpm)
{
    const float* A; const float* B; const float* bias; float* C; int N; int rowOff;
    switch (blockIdx.z) {
        case 0: A = Xa; B = W_rha; bias = b_rha; C = g_pre_rha; N = HS;  rowOff = 0;   break;
        case 1: A = Xm; B = W_rhm; bias = b_rhm; C = g_pre_rhm; N = HS;  rowOff = 0;   break;
        case 2: A = Xa; B = W_ca;  bias = b_ca;  C = g_pre_ca;  N = HS;  rowOff = HS;  break;
        case 3: A = Xm; B = W_cm;  bias = b_cm;  C = g_pre_cm;  N = HS;  rowOff = HS;  break;
        case 4: A = Xa; B = W_wpa; bias = b_wpa; C = g_pre_wpa; N = MBK; rowOff = HS;  break;
        default:A = Xm; B = W_wpm; bias = b_wpm; C = g_pre_wpm; N = MBK; rowOff = HS;  break;
    }
    if ((int)blockIdx.x * 128 >= N) return;

    const int K = INSZ;
    __shared__ float As[8][128];
    __shared__ float Bs[8][128];
    const int tid  = threadIdx.x;
    const int tx   = tid & 15, ty = tid >> 4;
    const int brow = blockIdx.y, bcol = blockIdx.x;

    const int arow = tid >> 1, akq = (tid & 1) * 4;
    const float* Ag = A + (size_t)(brow * 128 + arow) * K + akq;
    const int bk = tid >> 5, bc = (tid & 31) * 4;
    const int gcol = bcol * 128 + bc;
    const bool bok = (gcol + 3 < N);

    float acc[8][8];
#pragma unroll
    for (int i = 0; i < 8; i++)
#pragma unroll
        for (int j = 0; j < 8; j++) acc[i][j] = 0.f;

    for (int k0 = 0; k0 < K; k0 += 8) {
        float4 av = *(const float4*)(Ag + k0);
        As[akq + 0][arow] = av.x; As[akq + 1][arow] = av.y;
        As[akq + 2][arow] = av.z; As[akq + 3][arow] = av.w;
        float4 bv = bok ? *(const float4*)(B + (size_t)(rowOff + k0 + bk) * N + gcol)
                        : make_float4(0.f, 0.f, 0.f, 0.f);
        *(float4*)&Bs[bk][bc] = bv;
        __syncthreads();
#pragma unroll
        for (int kk = 0; kk < 8; ++kk) {
            float ra[8], rb[8];
            *(float4*)(ra)     = *(const float4*)&As[kk][ty * 4];
            *(float4*)(ra + 4) = *(const float4*)&As[kk][64 + ty * 4];
            *(float4*)(rb)     = *(const float4*)&Bs[kk][tx * 4];
            *(float4*)(rb + 4) = *(const float4*)&Bs[kk][64 + tx * 4];
#pragma unroll
            for (int i = 0; i < 8; i++)
#pragma unroll
                for (int j = 0; j < 8; j++) acc[i][j] = fmaf(ra[i], rb[j], acc[i][j]);
        }
        __syncthreads();
    }
#pragma unroll
    for (int i = 0; i < 8; i++) {
        int row = brow * 128 + ((i < 4) ? (ty * 4 + i) : (64 + ty * 4 + i - 4));
#pragma unroll
        for (int j = 0; j < 8; j++) {
            int col = bcol * 128 + ((j < 4) ? (tx * 4 + j) : (64 + tx * 4 + j - 4));
            if (col < N) C[(size_t)row * N + col] = acc[i][j] + bias[col];
        }
    }
}

// =====================================================================
// Persistent sequential kernel: 128 CTAs x 512 threads, each owns 4 HS columns.
// 2 grid barriers per step; prefetched per-step constants; in-register ar-softmax.
// =====================================================================
struct SeqSmem {
    float wrh [4][1024];   // W_rh  col slices: rows [r(512) | h(512)]
    float wrha[4][1024];   // W_rha rows 2048..3071: [r | ha]
    float wrhm[4][1024];   // W_rhm rows 2048..3071: [r | hm]
    float wca [4][512];    // W_ca rows 0..511 (ha)
    float wcm [4][512];    // W_cm rows 0..511 (hm)
    float wrp_r [12][104]; // W_rp rows owned x 100 logits
    float wwp_r [12][4];   // W_wp rows owned x 3
    float wwpa_r[4][104];  // W_wpa rows c4..+3 (ha part) x 100
    float wwpm_r[4][104];
    float mem [4][MBK];    // mem[:, owned cols], col-major
    float sx  [1536];      // state entering the step: [ha | hm | h]
    float r   [512];
    float lar [MBK], lawa[MBK], lawm[MBK], law[3];
    float pawa[MBK], pawm[MBK], aw[3];
    float snew[12];        // new state own comps: [ha1(4) | hm1(4) | h1(4)]
    float pre_ca[2][4], pre_cm[2][4], pre_rha[2][4], pre_rhm[2][4]; // double-buffered
    float pwa[2][MBK], pwm[2][MBK];                                 // double-buffered
    float ca_own[4], cm_own[4];
    float brh[4];
    float brp_s[MBK], bwp_s[3];
};

__global__ __launch_bounds__(NTHR, 1)
void seq_kernel(const float* __restrict__ W_ca,  const float* __restrict__ W_cm,
                const float* __restrict__ W_wp,  const float* __restrict__ b_wp,
                const float* __restrict__ W_wpa, const float* __restrict__ W_wpm,
                const float* __restrict__ W_rp,  const float* __restrict__ b_rp,
                const float* __restrict__ W_rh,  const float* __restrict__ b_rh,
                const float* __restrict__ W_rha, const float* __restrict__ W_rhm,
                float* __restrict__ out)
{
    extern __shared__ float smem_raw[];
    SeqSmem& s = *reinterpret_cast<SeqSmem*>(smem_raw);
    const int tid  = threadIdx.x;
    const int warp = tid >> 5, lane = tid & 31;
    const int cta  = blockIdx.x;
    const int c4   = cta * 4;

    // ---- one-time weight load ----
    for (int idx = tid; idx < 4 * 1024; idx += NTHR) {
        int col = idx & 3, i = idx >> 2;
        s.wrh [col][i] = __ldg(&W_rh [(size_t)i * HS + c4 + col]);
        s.wrha[col][i] = __ldg(&W_rha[(size_t)(INSZ + i) * HS + c4 + col]);
        s.wrhm[col][i] = __ldg(&W_rhm[(size_t)(INSZ + i) * HS + c4 + col]);
    }
    for (int idx = tid; idx < 4 * 512; idx += NTHR) {
        int col = idx & 3, i = idx >> 2;
        s.wca[col][i] = __ldg(&W_ca[(size_t)i * HS + c4 + col]);
        s.wcm[col][i] = __ldg(&W_cm[(size_t)i * HS + c4 + col]);
    }
    for (int idx = tid; idx < 12 * MBK; idx += NTHR) {
        int k = idx / MBK, j = idx % MBK;
        int row = (k < 4) ? (c4 + k) : (k < 8) ? (512 + c4 + k - 4) : (1024 + c4 + k - 8);
        s.wrp_r[k][j] = __ldg(&W_rp[(size_t)row * MBK + j]);
    }
    if (tid < 36) {
        int k = tid / 3, j = tid % 3;
        int row = (k < 4) ? (c4 + k) : (k < 8) ? (512 + c4 + k - 4) : (1024 + c4 + k - 8);
        s.wwp_r[k][j] = __ldg(&W_wp[(size_t)row * 3 + j]);
    }
    for (int idx = tid; idx < 4 * MBK; idx += NTHR) {
        int k = idx / MBK, j = idx % MBK;
        s.wwpa_r[k][j] = __ldg(&W_wpa[(size_t)(c4 + k) * MBK + j]);
        s.wwpm_r[k][j] = __ldg(&W_wpm[(size_t)(c4 + k) * MBK + j]);
    }
    for (int i = tid; i < MBK; i += NTHR) s.brp_s[i] = __ldg(&b_rp[i]);
    if (tid < 3) s.bwp_s[tid] = b_wp[tid];
    if (tid < 4) s.brh[tid] = b_rh[c4 + tid];
    for (int idx = tid; idx < 4 * MBK; idx += NTHR) (&s.mem[0][0])[idx] = 0.f;
    // t=0 per-step constants
    if (tid < 4) {
        s.pre_ca [0][tid] = __ldg(&g_pre_ca [c4 + tid]);
        s.pre_cm [0][tid] = __ldg(&g_pre_cm [c4 + tid]);
        s.pre_rha[0][tid] = __ldg(&g_pre_rha[c4 + tid]);
        s.pre_rhm[0][tid] = __ldg(&g_pre_rhm[c4 + tid]);
    }
    for (int j = tid; j < MBK; j += NTHR) {
        s.pwa[0][j] = __ldg(&g_pre_wpa[j]);
        s.pwm[0][j] = __ldg(&g_pre_wpm[j]);
    }
    __syncthreads();

    unsigned int barc = 0;

    for (int t = 0; t < T_STEPS; ++t) {
        const int buf  = t & 1;
        const int nbuf = buf ^ 1;

        // ============ phase A ============
        if (t == 0) {
            for (int i = tid; i < 1536; i += NTHR) s.sx[i] = 0.f;
        } else {
            for (int i = tid; i < 1536; i += NTHR) s.sx[i] = __ldcg(&g_state[i]);
        }
        if (tid < MBK) {
            s.lar [tid] = __ldcg(&g_acc[buf][tid])       + s.brp_s[tid];
            s.lawa[tid] = __ldcg(&g_acc[buf][103 + tid]) + s.pwa[buf][tid];
            s.lawm[tid] = __ldcg(&g_acc[buf][203 + tid]) + s.pwm[buf][tid];
        } else if (tid < MBK + 3) {
            s.law[tid - MBK] = __ldcg(&g_acc[buf][tid]) + s.bwp_s[tid - MBK];
        }
        __syncthreads();

        if (warp < 4) {
            // redundant in-register ar softmax + fused r-dot over OLD mem
            int col = warp;
            float v[4];
#pragma unroll
            for (int k = 0; k < 4; k++) { int j = lane + 32 * k; v[k] = (j < MBK) ? s.lar[j] : -1e30f; }
            float m = fmaxf(fmaxf(v[0], v[1]), fmaxf(v[2], v[3]));
#pragma unroll
            for (int o = 16; o; o >>= 1) m = fmaxf(m, __shfl_xor_sync(0xFFFFFFFFu, m, o));
            float e[4], sum = 0.f;
#pragma unroll
            for (int k = 0; k < 4; k++) {
                int j = lane + 32 * k;
                e[k] = (j < MBK) ? expf(v[k] - m) : 0.f;
                sum += e[k];
            }
            sum = warpsum(sum);
            float inv = 1.f / sum;
            float acc = 0.f;
#pragma unroll
            for (int k = 0; k < 4; k++) {
                int j = lane + 32 * k;
                if (j < MBK) acc = fmaf(e[k] * inv, s.mem[col][j], acc);
            }
            acc = warpsum(acc);
            if (lane == 0) __stcg(&g_r[c4 + col], acc);
        } else if (warp < 12) {
            // 8 content dots: warps 4-7 -> c_a cols, warps 8-11 -> c_m cols
            int col = warp & 3;
            bool isA = warp < 8;
            const float* w = isA ? s.wca[col] : s.wcm[col];
            const float* x = isA ? s.sx : (s.sx + 512);
            float acc = 0.f;
#pragma unroll
            for (int i = 0; i < 512; i += 32) acc = fmaf(x[i + lane], w[i + lane], acc);
            acc = warpsum(acc);
            if (lane == 0) {
                if (isA) s.ca_own[col] = fmaxf(acc + s.pre_ca[buf][col], 0.f);
                else     s.cm_own[col] = fmaxf(acc + s.pre_cm[buf][col], 0.f);
            }
        } else if (warp < 14) {
            // pawa / pawm softmaxes
            const float* L = (warp == 12) ? s.lawa : s.lawm;
            float* P       = (warp == 12) ? s.pawa : s.pawm;
            float v[4];
#pragma unroll
            for (int k = 0; k < 4; k++) { int j = lane + 32 * k; v[k] = (j < MBK) ? L[j] : -1e30f; }
            float m = fmaxf(fmaxf(v[0], v[1]), fmaxf(v[2], v[3]));
#pragma unroll
            for (int o = 16; o; o >>= 1) m = fmaxf(m, __shfl_xor_sync(0xFFFFFFFFu, m, o));
            float e[4], sum = 0.f;
#pragma unroll
            for (int k = 0; k < 4; k++) {
                int j = lane + 32 * k;
                e[k] = (j < MBK) ? expf(v[k] - m) : 0.f;
                sum += e[k];
            }
            sum = warpsum(sum);
            float inv = 1.f / sum;
#pragma unroll
            for (int k = 0; k < 4; k++) { int j = lane + 32 * k; if (j < MBK) P[j] = e[k] * inv; }
        } else if (warp == 14 && lane == 0) {
            float l0 = s.law[0], l1 = s.law[1], l2 = s.law[2];
            float m = fmaxf(l0, fmaxf(l1, l2));
            float e0 = expf(l0 - m), e1 = expf(l1 - m), e2 = expf(l2 - m);
            float inv = 1.f / (e0 + e1 + e2);
            s.aw[0] = e0 * inv; s.aw[1] = e1 * inv; s.aw[2] = e2 * inv;
        }

        ++barc; gbar_arrive();
        // mem update (purely local) overlaps the barrier wait
        for (int idx = tid; idx < 4 * MBK; idx += NTHR) {
            int col = idx & 3, j = idx >> 2;
            s.mem[col][j] = fmaf(s.aw[0], s.mem[col][j],
                            fmaf(s.aw[1] * s.pawa[j], s.ca_own[col],
                                 s.aw[2] * s.pawm[j] * s.cm_own[col]));
        }
        gbar_wait(barc * NCTA);

        // ============ phase B ============
        for (int i = tid; i < 512; i += NTHR) s.r[i] = __ldcg(&g_r[i]);
        // zero the just-consumed accumulator buffer (disjoint slices)
        if (warp == 15 && lane < 4 && cta < 80) __stcg(&g_acc[buf][c4 + lane], 0.f);
        // prefetch per-step constants for t+1 into the other buffer
        {
            int tn = (t + 1 < T_STEPS) ? (t + 1) : t;
            if (warp == 12 && lane < 16) {
                int a = lane >> 2, k = lane & 3;
                size_t off = (size_t)tn * HS + c4 + k;
                if (a == 0)      s.pre_ca [nbuf][k] = __ldcg(&g_pre_ca [off]);
                else if (a == 1) s.pre_cm [nbuf][k] = __ldcg(&g_pre_cm [off]);
                else if (a == 2) s.pre_rha[nbuf][k] = __ldcg(&g_pre_rha[off]);
                else             s.pre_rhm[nbuf][k] = __ldcg(&g_pre_rhm[off]);
            }
            if (warp == 13) for (int j = lane; j < MBK; j += 32) s.pwa[nbuf][j] = __ldcg(&g_pre_wpa[(size_t)tn * MBK + j]);
            if (warp == 14) for (int j = lane; j < MBK; j += 32) s.pwm[nbuf][j] = __ldcg(&g_pre_wpm[(size_t)tn * MBK + j]);
        }
        __syncthreads();

        if (warp < 12) {
            int mat = warp >> 2, col = warp & 3;
            const float* w = (mat == 0) ? s.wrh[col] : (mat == 1) ? s.wrha[col] : s.wrhm[col];
            const float* x = (mat == 0) ? (s.sx + 1024) : (mat == 1) ? s.sx : (s.sx + 512);
            float acc = 0.f;
#pragma unroll
            for (int i = lane; i < 512; i += 32)
                acc = fmaf(s.r[i], w[i], fmaf(x[i], w[512 + i], acc));
            acc = warpsum(acc);
            if (lane == 0) {
                if (mat == 0) {
                    float h1 = fmaxf(acc + s.brh[col], 0.f);
                    s.snew[8 + col] = h1;
                    __stcg(&g_state[1024 + c4 + col], h1);
                    out[(size_t)t * HS + c4 + col] = h1;
                } else if (mat == 1) {
                    float ha1 = fmaxf(acc + s.pre_rha[buf][col], 0.f);
                    s.snew[col] = ha1;
                    __stcg(&g_state[c4 + col], ha1);
                } else {
                    float hm1 = fmaxf(acc + s.pre_rhm[buf][col], 0.f);
                    s.snew[4 + col] = hm1;
                    __stcg(&g_state[512 + c4 + col], hm1);
                }
            }
        }
        __syncthreads();

        // push partial logits for step t+1 (303 spread-address float REDs)
        if (t + 1 < T_STEPS && tid < 303) {
            float p = 0.f;
            int slot;
            if (tid < MBK) {
#pragma unroll
                for (int k = 0; k < 12; k++) p = fmaf(s.snew[k], s.wrp_r[k][tid], p);
                slot = tid;
            } else if (tid < MBK + 3) {
                int j = tid - MBK;
#pragma unroll
                for (int k = 0; k < 12; k++) p = fmaf(s.snew[k], s.wwp_r[k][j], p);
                slot = 100 + j;
            } else if (tid < 203) {
                int j = tid - 103;
#pragma unroll
                for (int k = 0; k < 4; k++) p = fmaf(s.snew[k], s.wwpa_r[k][j], p);
                slot = 103 + j;
            } else {
                int j = tid - 203;
#pragma unroll
                for (int k = 0; k < 4; k++) p = fmaf(s.snew[4 + k], s.wwpm_r[k][j], p);
                slot = 203 + j;
            }
            atomicAdd(&g_acc[nbuf][slot], p);
        }
        ++barc; gbar_arrive(); gbar_wait(barc * NCTA);
    }
}

// =====================================================================
extern "C" void kernel_launch(void* const* d_in, const int* in_sizes, int n_in,
                              void* d_out, int out_size)
{
    const float* Xa    = (const float*)d_in[0];
    const float* Xm    = (const float*)d_in[1];
    const float* W_ca  = (const float*)d_in[2];
    const float* b_ca  = (const float*)d_in[3];
    const float* W_cm  = (const float*)d_in[4];
    const float* b_cm  = (const float*)d_in[5];
    const float* W_wp  = (const float*)d_in[6];
    const float* b_wp  = (const float*)d_in[7];
    const float* W_wpa = (const float*)d_in[8];
    const float* b_wpa = (const float*)d_in[9];
    const float* W_wpm = (const float*)d_in[10];
    const float* b_wpm = (const float*)d_in[11];
    const float* W_rp  = (const float*)d_in[12];
    const float* b_rp  = (const float*)d_in[13];
    const float* W_rh  = (const float*)d_in[14];
    const float* b_rh  = (const float*)d_in[15];
    const float* W_rha = (const float*)d_in[16];
    const float* W_rhm = (const float*)d_in[18];
    float* out = (float*)d_out;

    static bool attr_set = false;
    if (!attr_set) {
        cudaFuncSetAttribute(seq_kernel, cudaFuncAttributeMaxDynamicSharedMemorySize,
                             (int)sizeof(SeqSmem));
        attr_set = true;
    }

    dim3 ggrid(4, T_STEPS / 128, 6);
    gemm6_kernel<<<ggrid, 256>>>(Xa, Xm,
                                 W_rha, (const float*)d_in[17],
                                 W_rhm, (const float*)d_in[19],
                                 W_ca, b_ca, W_cm, b_cm,
                                 W_wpa, b_wpa, W_wpm, b_wpm);
    reset_kernel<<<1, 512>>>();
    seq_kernel<<<NCTA, NTHR, sizeof(SeqSmem)>>>(W_ca, W_cm, W_wp, b_wp, W_wpa, W_wpm,
                                                W_rp, b_rp, W_rh, b_rh, W_rha, W_rhm,
                                                out);
}

// round 11
// speedup vs baseline: 1.1145x; 1.1145x over previous
#include <cuda_runtime.h>
#include <cuda_bf16.h>
#include <math.h>
#include <stdint.h>

#define T_STEPS 4096
#define HS 512
#define INSZ 2048
#define MBK 100
#define NCTA 64
#define NTHR 512
#define NCOL 8

// ---------------- device scratch (allocations are forbidden) ----------------
__device__ float g_pre_rha[T_STEPS * HS];
__device__ float g_pre_rhm[T_STEPS * HS];
__device__ float g_pre_ca [T_STEPS * HS];
__device__ float g_pre_cm [T_STEPS * HS];
__device__ float g_pre_wpa[T_STEPS * MBK];
__device__ float g_pre_wpm[T_STEPS * MBK];
__device__ float g_state[3 * HS];          // [ha(512) | hm(512) | h(512)]
__device__ float g_r[HS];
// logit accumulators, double buffered: [0..99]=ar, [100..102]=aw,
// [103..202]=aw_a(ha part), [203..302]=aw_m(hm part)
__device__ float g_acc[2][320];
__device__ unsigned int g_bar;

__device__ __forceinline__ float warpsum(float v) {
#pragma unroll
    for (int o = 16; o; o >>= 1) v += __shfl_xor_sync(0xFFFFFFFFu, v, o);
    return v;
}

// ---------------- single-counter grid barrier, split arrive/wait ----------------
__device__ __forceinline__ void gbar_arrive() {
    __syncthreads();
    if (threadIdx.x == 0) {
        __threadfence();
        atomicAdd(&g_bar, 1u);
    }
}
__device__ __forceinline__ void gbar_wait(unsigned int target) {
    if (threadIdx.x == 0) {
        int spins = 0;
        while (*(volatile unsigned int*)&g_bar < target) {
            if (++spins > 8) __nanosleep(40);
        }
        __threadfence();
    }
    __syncthreads();
}

__global__ void reset_kernel() {
    int i = threadIdx.x;
    if (i == 0) g_bar = 0u;
    float* a = &g_acc[0][0];
    for (int j = i; j < 2 * 320; j += blockDim.x) a[j] = 0.f;
}

// =====================================================================
// Precompute GEMMs: C[4096,N] = X @ W[rowOff:+2048, :N] + bias (6 jobs in z)
// =====================================================================
__global__ __launch_bounds__(256)
void gemm6_kernel(const float* __restrict__ Xa, const float* __restrict__ Xm,
                  const float* __restrict__ W_rha, const float* __restrict__ b_rha,
                  const float* __restrict__ W_rhm, const float* __restrict__ b_rhm,
                  const float* __restrict__ W_ca,  const float* __restrict__ b_ca,
                  const float* __restrict__ W_cm,  const float* __restrict__ b_cm,
                  const float* __restrict__ W_wpa, const float* __restrict__ b_wpa,
                  const float* __restrict__ W_wpm, const float* __restrict__ b_wpm)
{
    const float* A; const float* B; const float* bias; float* C; int N; int rowOff;
    switch (blockIdx.z) {
        case 0: A = Xa; B = W_rha; bias = b_rha; C = g_pre_rha; N = HS;  rowOff = 0;   break;
        case 1: A = Xm; B = W_rhm; bias = b_rhm; C = g_pre_rhm; N = HS;  rowOff = 0;   break;
        case 2: A = Xa; B = W_ca;  bias = b_ca;  C = g_pre_ca;  N = HS;  rowOff = HS;  break;
        case 3: A = Xm; B = W_cm;  bias = b_cm;  C = g_pre_cm;  N = HS;  rowOff = HS;  break;
        case 4: A = Xa; B = W_wpa; bias = b_wpa; C = g_pre_wpa; N = MBK; rowOff = HS;  break;
        default:A = Xm; B = W_wpm; bias = b_wpm; C = g_pre_wpm; N = MBK; rowOff = HS;  break;
    }
    if ((int)blockIdx.x * 128 >= N) return;

    const int K = INSZ;
    __shared__ float As[8][128];
    __shared__ float Bs[8][128];
    const int tid  = threadIdx.x;
    const int tx   = tid & 15, ty = tid >> 4;
    const int brow = blockIdx.y, bcol = blockIdx.x;

    const int arow = tid >> 1, akq = (tid & 1) * 4;
    const float* Ag = A + (size_t)(brow * 128 + arow) * K + akq;
    const int bk = tid >> 5, bc = (tid & 31) * 4;
    const int gcol = bcol * 128 + bc;
    const bool bok = (gcol + 3 < N);

    float acc[8][8];
#pragma unroll
    for (int i = 0; i < 8; i++)
#pragma unroll
        for (int j = 0; j < 8; j++) acc[i][j] = 0.f;

    for (int k0 = 0; k0 < K; k0 += 8) {
        float4 av = *(const float4*)(Ag + k0);
        As[akq + 0][arow] = av.x; As[akq + 1][arow] = av.y;
        As[akq + 2][arow] = av.z; As[akq + 3][arow] = av.w;
        float4 bv = bok ? *(const float4*)(B + (size_t)(rowOff + k0 + bk) * N + gcol)
                        : make_float4(0.f, 0.f, 0.f, 0.f);
        *(float4*)&Bs[bk][bc] = bv;
        __syncthreads();
#pragma unroll
        for (int kk = 0; kk < 8; ++kk) {
            float ra[8], rb[8];
            *(float4*)(ra)     = *(const float4*)&As[kk][ty * 4];
            *(float4*)(ra + 4) = *(const float4*)&As[kk][64 + ty * 4];
            *(float4*)(rb)     = *(const float4*)&Bs[kk][tx * 4];
            *(float4*)(rb + 4) = *(const float4*)&Bs[kk][64 + tx * 4];
#pragma unroll
            for (int i = 0; i < 8; i++)
#pragma unroll
                for (int j = 0; j < 8; j++) acc[i][j] = fmaf(ra[i], rb[j], acc[i][j]);
        }
        __syncthreads();
    }
#pragma unroll
    for (int i = 0; i < 8; i++) {
        int row = brow * 128 + ((i < 4) ? (ty * 4 + i) : (64 + ty * 4 + i - 4));
#pragma unroll
        for (int j = 0; j < 8; j++) {
            int col = bcol * 128 + ((j < 4) ? (tx * 4 + j) : (64 + tx * 4 + j - 4));
            if (col < N) C[(size_t)row * N + col] = acc[i][j] + bias[col];
        }
    }
}

// =====================================================================
// Persistent sequential kernel: 64 CTAs x 512 threads, each owns 8 HS columns.
// 2 grid barriers per step (logits pushed forward from phase B). R9 structure.
// =====================================================================
struct SeqSmem {
    float wrh [NCOL][1024];   // W_rh  col slices: rows [r(512) | h(512)]
    float wrha[NCOL][1024];   // W_rha rows 2048..3071: [r | ha]
    float wrhm[NCOL][1024];   // W_rhm rows 2048..3071: [r | hm]
    float wca [NCOL][512];    // W_ca rows 0..511 (ha)
    float wcm [NCOL][512];    // W_cm rows 0..511 (hm)
    float wrp_r [24][104];    // W_rp rows owned (ha0-7,hm0-7,h0-7) x 100 logits
    float wwp_r [24][4];      // W_wp rows owned x 3
    float wwpa_r[NCOL][104];  // W_wpa rows c8..+7 (ha part) x 100
    float wwpm_r[NCOL][104];
    float mem [NCOL][MBK];    // mem[:, owned cols], col-major
    float sx  [1536];         // state entering the step: [ha | hm | h]
    float r   [512];
    float lar [MBK], lawa[MBK], lawm[MBK], law[3];
    float par [MBK], pawa[MBK], pawm[MBK], aw[3];
    float snew[24];           // new state own comps: [ha1(8) | hm1(8) | h1(8)]
    float pre_ca[NCOL], pre_cm[NCOL], pre_rha[NCOL], pre_rhm[NCOL];
    float ca_own[NCOL], cm_own[NCOL];
    float brh[NCOL];
    float brp_s[MBK], bwp_s[3];
};

__global__ __launch_bounds__(NTHR, 1)
void seq_kernel(const float* __restrict__ W_ca,  const float* __restrict__ W_cm,
                const float* __restrict__ W_wp,  const float* __restrict__ b_wp,
                const float* __restrict__ W_wpa, const float* __restrict__ W_wpm,
                const float* __restrict__ W_rp,  const float* __restrict__ b_rp,
                const float* __restrict__ W_rh,  const float* __restrict__ b_rh,
                const float* __restrict__ W_rha, const float* __restrict__ W_rhm,
                float* __restrict__ out)
{
    extern __shared__ float smem_raw[];
    SeqSmem& s = *reinterpret_cast<SeqSmem*>(smem_raw);
    const int tid  = threadIdx.x;
    const int warp = tid >> 5, lane = tid & 31;
    const int cta  = blockIdx.x;
    const int c8   = cta * NCOL;

    // ---- one-time weight load (column slices, column-major in SMEM) ----
    for (int idx = tid; idx < NCOL * 1024; idx += NTHR) {
        int col = idx & (NCOL - 1), i = idx >> 3;
        s.wrh [col][i] = __ldg(&W_rh [(size_t)i * HS + c8 + col]);
        s.wrha[col][i] = __ldg(&W_rha[(size_t)(INSZ + i) * HS + c8 + col]);
        s.wrhm[col][i] = __ldg(&W_rhm[(size_t)(INSZ + i) * HS + c8 + col]);
    }
    for (int idx = tid; idx < NCOL * 512; idx += NTHR) {
        int col = idx & (NCOL - 1), i = idx >> 3;
        s.wca[col][i] = __ldg(&W_ca[(size_t)i * HS + c8 + col]);
        s.wcm[col][i] = __ldg(&W_cm[(size_t)i * HS + c8 + col]);
    }
    // push-weight rows (owned state dims -> all logits)
    for (int idx = tid; idx < 24 * MBK; idx += NTHR) {
        int k = idx / MBK, j = idx % MBK;
        int row = (k < 8) ? (c8 + k) : (k < 16) ? (512 + c8 + k - 8) : (1024 + c8 + k - 16);
        s.wrp_r[k][j] = __ldg(&W_rp[(size_t)row * MBK + j]);
    }
    if (tid < 72) {
        int k = tid / 3, j = tid % 3;
        int row = (k < 8) ? (c8 + k) : (k < 16) ? (512 + c8 + k - 8) : (1024 + c8 + k - 16);
        s.wwp_r[k][j] = __ldg(&W_wp[(size_t)row * 3 + j]);
    }
    for (int idx = tid; idx < NCOL * MBK; idx += NTHR) {
        int k = idx / MBK, j = idx % MBK;
        s.wwpa_r[k][j] = __ldg(&W_wpa[(size_t)(c8 + k) * MBK + j]);
        s.wwpm_r[k][j] = __ldg(&W_wpm[(size_t)(c8 + k) * MBK + j]);
    }
    for (int i = tid; i < MBK; i += NTHR) s.brp_s[i] = __ldg(&b_rp[i]);
    if (tid < 3) s.bwp_s[tid] = b_wp[tid];
    if (tid < NCOL) s.brh[tid] = b_rh[c8 + tid];
    for (int idx = tid; idx < NCOL * MBK; idx += NTHR) (&s.mem[0][0])[idx] = 0.f;
    __syncthreads();

    unsigned int barc = 0;

    for (int t = 0; t < T_STEPS; ++t) {
        const int buf  = t & 1;
        const int nbuf = buf ^ 1;

        // ============ phase A: read state+logits, softmax, c dots, r + mem ============
        if (t == 0) {
            for (int i = tid; i < 1536; i += NTHR) s.sx[i] = 0.f;
        } else {
            for (int i = tid; i < 1536; i += NTHR) s.sx[i] = __ldcg(&g_state[i]);
        }
        if (tid < MBK) {
            s.lar [tid] = __ldcg(&g_acc[buf][tid])       + s.brp_s[tid];
            s.lawa[tid] = __ldcg(&g_acc[buf][103 + tid]) + __ldcg(&g_pre_wpa[(size_t)t * MBK + tid]);
            s.lawm[tid] = __ldcg(&g_acc[buf][203 + tid]) + __ldcg(&g_pre_wpm[(size_t)t * MBK + tid]);
        } else if (tid < MBK + 3) {
            s.law[tid - MBK] = __ldcg(&g_acc[buf][tid]) + s.bwp_s[tid - MBK];
        }
        if (tid < NCOL) {
            s.pre_ca [tid] = __ldcg(&g_pre_ca [(size_t)t * HS + c8 + tid]);
            s.pre_cm [tid] = __ldcg(&g_pre_cm [(size_t)t * HS + c8 + tid]);
            s.pre_rha[tid] = __ldcg(&g_pre_rha[(size_t)t * HS + c8 + tid]);
            s.pre_rhm[tid] = __ldcg(&g_pre_rhm[(size_t)t * HS + c8 + tid]);
        }
        __syncthreads();

        // warps 0-7: c_a col + c_m col (two dots each); warps 8-10: softmaxes; warp 11: aw
        if (warp < 8) {
            int col = warp;
            float accA = 0.f, accM = 0.f;
#pragma unroll
            for (int i = 0; i < 512; i += 32) {
                accA = fmaf(s.sx[i + lane],       s.wca[col][i + lane], accA);
                accM = fmaf(s.sx[512 + i + lane], s.wcm[col][i + lane], accM);
            }
            accA = warpsum(accA);
            accM = warpsum(accM);
            if (lane == 0) {
                s.ca_own[col] = fmaxf(accA + s.pre_ca[col], 0.f);
                s.cm_own[col] = fmaxf(accM + s.pre_cm[col], 0.f);
            }
        } else if (warp < 11) {
            const float* L = (warp == 8) ? s.lar : (warp == 9) ? s.lawa : s.lawm;
            float* P       = (warp == 8) ? s.par : (warp == 9) ? s.pawa : s.pawm;
            float v[4];
#pragma unroll
            for (int k = 0; k < 4; k++) { int j = lane + 32 * k; v[k] = (j < MBK) ? L[j] : -1e30f; }
            float m = fmaxf(fmaxf(v[0], v[1]), fmaxf(v[2], v[3]));
#pragma unroll
            for (int o = 16; o; o >>= 1) m = fmaxf(m, __shfl_xor_sync(0xFFFFFFFFu, m, o));
            float e[4], sum = 0.f;
#pragma unroll
            for (int k = 0; k < 4; k++) {
                int j = lane + 32 * k;
                e[k] = (j < MBK) ? expf(v[k] - m) : 0.f;
                sum += e[k];
            }
            sum = warpsum(sum);
            float inv = 1.f / sum;
#pragma unroll
            for (int k = 0; k < 4; k++) { int j = lane + 32 * k; if (j < MBK) P[j] = e[k] * inv; }
        } else if (warp == 11 && lane == 0) {
            float l0 = s.law[0], l1 = s.law[1], l2 = s.law[2];
            float m = fmaxf(l0, fmaxf(l1, l2));
            float e0 = expf(l0 - m), e1 = expf(l1 - m), e2 = expf(l2 - m);
            float inv = 1.f / (e0 + e1 + e2);
            s.aw[0] = e0 * inv; s.aw[1] = e1 * inv; s.aw[2] = e2 * inv;
        }
        __syncthreads();

        // warps 0-7: r-dot over OLD mem for owned col
        if (warp < 8) {
            int col = warp;
            float acc = 0.f;
#pragma unroll
            for (int k = 0; k < 4; k++) {
                int j = lane + 32 * k;
                if (j < MBK) acc = fmaf(s.par[j], s.mem[col][j], acc);
            }
            acc = warpsum(acc);
            if (lane == 0) __stcg(&g_r[c8 + col], acc);
        }
        ++barc; gbar_arrive();

        // mem update (purely local) overlaps the barrier wait
        {
            float aw0 = s.aw[0], aw1 = s.aw[1], aw2 = s.aw[2];
            for (int idx = tid; idx < NCOL * MBK; idx += NTHR) {
                int col = idx & (NCOL - 1), j = idx >> 3;
                s.mem[col][j] = fmaf(aw0, s.mem[col][j],
                                fmaf(aw1 * s.pawa[j], s.ca_own[col],
                                     aw2 * s.pawm[j] * s.cm_own[col]));
            }
        }
        gbar_wait(barc * NCTA);

        // ============ phase B: h1/ha1/hm1 dots + push next-step logits ============
        for (int i = tid; i < 512; i += NTHR) s.r[i] = __ldcg(&g_r[i]);
        // zero the just-consumed accumulator buffer (disjoint slices)
        if (warp == 15 && lane < NCOL && c8 + lane < 320 && cta < 40)
            __stcg(&g_acc[buf][c8 + lane], 0.f);
        __syncthreads();

        // 24 warp-dots over 16 warps: round 1 = tasks 0..15, round 2 = tasks 16..23
#pragma unroll
        for (int rep = 0; rep < 2; rep++) {
            int task = warp + rep * 16;
            if (task < 24) {
                int mat = task >> 3, col = task & (NCOL - 1);
                const float* w = (mat == 0) ? s.wrh[col] : (mat == 1) ? s.wrha[col] : s.wrhm[col];
                const float* x = (mat == 0) ? (s.sx + 1024) : (mat == 1) ? s.sx : (s.sx + 512);
                float acc = 0.f;
#pragma unroll
                for (int i = lane; i < 512; i += 32)
                    acc = fmaf(s.r[i], w[i], fmaf(x[i], w[512 + i], acc));
                acc = warpsum(acc);
                if (lane == 0) {
                    if (mat == 0) {
                        float h1 = fmaxf(acc + s.brh[col], 0.f);
                        s.snew[16 + col] = h1;
                        __stcg(&g_state[1024 + c8 + col], h1);
                        out[(size_t)t * HS + c8 + col] = h1;
                    } else if (mat == 1) {
                        float ha1 = fmaxf(acc + s.pre_rha[col], 0.f);
                        s.snew[col] = ha1;
                        __stcg(&g_state[c8 + col], ha1);
                    } else {
                        float hm1 = fmaxf(acc + s.pre_rhm[col], 0.f);
                        s.snew[8 + col] = hm1;
                        __stcg(&g_state[512 + c8 + col], hm1);
                    }
                }
            }
        }
        __syncthreads();

        // push partial logits for step t+1 (303 spread-address float REDs)
        if (t + 1 < T_STEPS && tid < 303) {
            float p = 0.f;
            int slot;
            if (tid < MBK) {                       // ar logit
#pragma unroll
                for (int k = 0; k < 24; k++) p = fmaf(s.snew[k], s.wrp_r[k][tid], p);
                slot = tid;
            } else if (tid < MBK + 3) {            // aw logit
                int j = tid - MBK;
#pragma unroll
                for (int k = 0; k < 24; k++) p = fmaf(s.snew[k], s.wwp_r[k][j], p);
                slot = 100 + j;
            } else if (tid < 203) {                // aw_a (ha part)
                int j = tid - 103;
#pragma unroll
                for (int k = 0; k < NCOL; k++) p = fmaf(s.snew[k], s.wwpa_r[k][j], p);
                slot = 103 + j;
            } else {                               // aw_m (hm part)
                int j = tid - 203;
#pragma unroll
                for (int k = 0; k < NCOL; k++) p = fmaf(s.snew[8 + k], s.wwpm_r[k][j], p);
                slot = 203 + j;
            }
            atomicAdd(&g_acc[nbuf][slot], p);
        }
        ++barc; gbar_arrive(); gbar_wait(barc * NCTA);
    }
}

// =====================================================================
extern "C" void kernel_launch(void* const* d_in, const int* in_sizes, int n_in,
                              void* d_out, int out_size)
{
    const float* Xa    = (const float*)d_in[0];
    const float* Xm    = (const float*)d_in[1];
    const float* W_ca  = (const float*)d_in[2];
    const float* b_ca  = (const float*)d_in[3];
    const float* W_cm  = (const float*)d_in[4];
    const float* b_cm  = (const float*)d_in[5];
    const float* W_wp  = (const float*)d_in[6];
    const float* b_wp  = (const float*)d_in[7];
    const float* W_wpa = (const float*)d_in[8];
    const float* b_wpa = (const float*)d_in[9];
    const float* W_wpm = (const float*)d_in[10];
    const float* b_wpm = (const float*)d_in[11];
    const float* W_rp  = (const float*)d_in[12];
    const float* b_rp  = (const float*)d_in[13];
    const float* W_rh  = (const float*)d_in[14];
    const float* b_rh  = (const float*)d_in[15];
    const float* W_rha = (const float*)d_in[16];
    const float* W_rhm = (const float*)d_in[18];
    float* out = (float*)d_out;

    static bool attr_set = false;
    if (!attr_set) {
        cudaFuncSetAttribute(seq_kernel, cudaFuncAttributeMaxDynamicSharedMemorySize,
                             (int)sizeof(SeqSmem));
        attr_set = true;
    }

    dim3 ggrid(4, T_STEPS / 128, 6);
    gemm6_kernel<<<ggrid, 256>>>(Xa, Xm,
                                 W_rha, (const float*)d_in[17],
                                 W_rhm, (const float*)d_in[19],
                                 W_ca, b_ca, W_cm, b_cm,
                                 W_wpa, b_wpa, W_wpm, b_wpm);
    reset_kernel<<<1, 512>>>();
    seq_kernel<<<NCTA, NTHR, sizeof(SeqSmem)>>>(W_ca, W_cm, W_wp, b_wp, W_wpa, W_wpm,
                                                W_rp, b_rp, W_rh, b_rh, W_rha, W_rhm,
                                                out);
}

// round 12
// speedup vs baseline: 1.1668x; 1.0469x over previous
#include <cuda_runtime.h>
#include <cuda_bf16.h>
#include <math.h>
#include <stdint.h>

#define T_STEPS 4096
#define HS 512
#define INSZ 2048
#define MBK 100
#define NCTA 128
#define NTHR 512

// ---------------- device scratch (allocations are forbidden) ----------------
__device__ float g_pre_rha[T_STEPS * HS];
__device__ float g_pre_rhm[T_STEPS * HS];
__device__ float g_pre_ca [T_STEPS * HS];
__device__ float g_pre_cm [T_STEPS * HS];
__device__ float g_pre_wpa[T_STEPS * MBK];
__device__ float g_pre_wpm[T_STEPS * MBK];
__device__ float g_state[3 * HS];          // [ha(512) | hm(512) | h(512)]
__device__ float g_r[HS];
// logit accumulators, double buffered: [0..99]=ar, [100..102]=aw,
// [103..202]=aw_a(ha part), [203..302]=aw_m(hm part)
__device__ float g_acc[2][320];
__device__ unsigned int g_bar;

__device__ __forceinline__ float warpsum(float v) {
#pragma unroll
    for (int o = 16; o; o >>= 1) v += __shfl_xor_sync(0xFFFFFFFFu, v, o);
    return v;
}

__device__ __forceinline__ unsigned int ld_acq(const unsigned int* p) {
    unsigned int v;
    asm volatile("ld.global.acquire.gpu.u32 %0, [%1];" : "=r"(v) : "l"(p));
    return v;
}

// arrive: release-atomic (orders all prior .cg stores); no MEMBAR needed
__device__ __forceinline__ void gbar_arrive() {
    __syncthreads();
    if (threadIdx.x == 0)
        asm volatile("red.release.gpu.global.add.u32 [%0], 1;" :: "l"(&g_bar) : "memory");
}
// wait: warp 15 polls global with acquire, publishes epoch to SMEM; others spin SMEM.
// NO trailing __syncthreads — each warp proceeds as soon as it observes the epoch.
__device__ __forceinline__ void gbar_wait(unsigned int target, volatile unsigned int* epoch) {
    const int warp = threadIdx.x >> 5, lane = threadIdx.x & 31;
    if (warp == 15) {
        if (lane == 0) {
            int sp = 0;
            unsigned int v;
            do {
                v = ld_acq(&g_bar);
                if (v < target && ++sp > 4) __nanosleep(20);
            } while (v < target);
            *epoch = target;
        }
        __syncwarp();
    } else {
        if (lane == 0) { while (*epoch < target) {} }
        __syncwarp();
    }
}

__global__ void reset_kernel() {
    int i = threadIdx.x;
    if (i == 0) g_bar = 0u;
    float* a = &g_acc[0][0];
    for (int j = i; j < 2 * 320; j += blockDim.x) a[j] = 0.f;
}

// =====================================================================
// Precompute GEMMs: C[4096,N] = X @ W[rowOff:+2048, :N] + bias (6 jobs in z)
// =====================================================================
__global__ __launch_bounds__(256)
void gemm6_kernel(const float* __restrict__ Xa, const float* __restrict__ Xm,
                  const float* __restrict__ W_rha, const float* __restrict__ b_rha,
                  const float* __restrict__ W_rhm, const float* __restrict__ b_rhm,
                  const float* __restrict__ W_ca,  const float* __restrict__ b_ca,
                  const float* __restrict__ W_cm,  const float* __restrict__ b_cm,
                  const float* __restrict__ W_wpa, const float* __restrict__ b_wpa,
                  const float* __restrict__ W_wpm, const float* __restrict__ b_wpm)
{
    const float* A; const float* B; const float* bias; float* C; int N; int rowOff;
    switch (blockIdx.z) {
        case 0: A = Xa; B = W_rha; bias = b_rha; C = g_pre_rha; N = HS;  rowOff = 0;   break;
        case 1: A = Xm; B = W_rhm; bias = b_rhm; C = g_pre_rhm; N = HS;  rowOff = 0;   break;
        case 2: A = Xa; B = W_ca;  bias = b_ca;  C = g_pre_ca;  N = HS;  rowOff = HS;  break;
        case 3: A = Xm; B = W_cm;  bias = b_cm;  C = g_pre_cm;  N = HS;  rowOff = HS;  break;
        case 4: A = Xa; B = W_wpa; bias = b_wpa; C = g_pre_wpa; N = MBK; rowOff = HS;  break;
        default:A = Xm; B = W_wpm; bias = b_wpm; C = g_pre_wpm; N = MBK; rowOff = HS;  break;
    }
    if ((int)blockIdx.x * 128 >= N) return;

    const int K = INSZ;
    __shared__ float As[8][128];
    __shared__ float Bs[8][128];
    const int tid  = threadIdx.x;
    const int tx   = tid & 15, ty = tid >> 4;
    const int brow = blockIdx.y, bcol = blockIdx.x;

    const int arow = tid >> 1, akq = (tid & 1) * 4;
    const float* Ag = A + (size_t)(brow * 128 + arow) * K + akq;
    const int bk = tid >> 5, bc = (tid & 31) * 4;
    const int gcol = bcol * 128 + bc;
    const bool bok = (gcol + 3 < N);

    float acc[8][8];
#pragma unroll
    for (int i = 0; i < 8; i++)
#pragma unroll
        for (int j = 0; j < 8; j++) acc[i][j] = 0.f;

    for (int k0 = 0; k0 < K; k0 += 8) {
        float4 av = *(const float4*)(Ag + k0);
        As[akq + 0][arow] = av.x; As[akq + 1][arow] = av.y;
        As[akq + 2][arow] = av.z; As[akq + 3][arow] = av.w;
        float4 bv = bok ? *(const float4*)(B + (size_t)(rowOff + k0 + bk) * N + gcol)
                        : make_float4(0.f, 0.f, 0.f, 0.f);
        *(float4*)&Bs[bk][bc] = bv;
        __syncthreads();
#pragma unroll
        for (int kk = 0; kk < 8; ++kk) {
            float ra[8], rb[8];
            *(float4*)(ra)     = *(const float4*)&As[kk][ty * 4];
            *(float4*)(ra + 4) = *(const float4*)&As[kk][64 + ty * 4];
            *(float4*)(rb)     = *(const float4*)&Bs[kk][tx * 4];
            *(float4*)(rb + 4) = *(const float4*)&Bs[kk][64 + tx * 4];
#pragma unroll
            for (int i = 0; i < 8; i++)
#pragma unroll
                for (int j = 0; j < 8; j++) acc[i][j] = fmaf(ra[i], rb[j], acc[i][j]);
        }
        __syncthreads();
    }
#pragma unroll
    for (int i = 0; i < 8; i++) {
        int row = brow * 128 + ((i < 4) ? (ty * 4 + i) : (64 + ty * 4 + i - 4));
#pragma unroll
        for (int j = 0; j < 8; j++) {
            int col = bcol * 128 + ((j < 4) ? (tx * 4 + j) : (64 + tx * 4 + j - 4));
            if (col < N) C[(size_t)row * N + col] = acc[i][j] + bias[col];
        }
    }
}

// =====================================================================
// Persistent sequential kernel: 128 CTAs x 512 threads, each owns 4 HS columns.
// 2 global rounds per step; fence-free release/acquire barrier; x-part hoisted.
// =====================================================================
struct SeqSmem {
    float wrh [4][1024];   // W_rh  col slices: rows [r(512) | h(512)]
    float wrha[4][1024];   // W_rha rows 2048..3071: [r | ha]
    float wrhm[4][1024];   // W_rhm rows 2048..3071: [r | hm]
    float wca [4][512];    // W_ca rows 0..511 (ha)
    float wcm [4][512];    // W_cm rows 0..511 (hm)
    float wrp_r [12][104]; // W_rp rows owned x 100 logits
    float wwp_r [12][4];   // W_wp rows owned x 3
    float wwpa_r[4][104];  // W_wpa rows c4..+3 (ha part) x 100
    float wwpm_r[4][104];
    float mem [4][MBK];    // mem[:, owned cols], col-major
    float sx  [1536];      // state entering the step: [ha | hm | h]
    float r   [512];
    float lar [MBK], lawa[MBK], lawm[MBK], law[3];
    float par [MBK], pawa[MBK], pawm[MBK], aw[3];
    float snew[12];        // new state own comps: [ha1(4) | hm1(4) | h1(4)]
    float pre_ca[4], pre_cm[4], pre_rha[4], pre_rhm[4];
    float ca_own[4], cm_own[4];
    float brh[4];
    float brp_s[MBK], bwp_s[3];
    unsigned int epoch;
};

__global__ __launch_bounds__(NTHR, 1)
void seq_kernel(const float* __restrict__ W_ca,  const float* __restrict__ W_cm,
                const float* __restrict__ W_wp,  const float* __restrict__ b_wp,
                const float* __restrict__ W_wpa, const float* __restrict__ W_wpm,
                const float* __restrict__ W_rp,  const float* __restrict__ b_rp,
                const float* __restrict__ W_rh,  const float* __restrict__ b_rh,
                const float* __restrict__ W_rha, const float* __restrict__ W_rhm,
                float* __restrict__ out)
{
    extern __shared__ float smem_raw[];
    SeqSmem& s = *reinterpret_cast<SeqSmem*>(smem_raw);
    const int tid  = threadIdx.x;
    const int warp = tid >> 5, lane = tid & 31;
    const int cta  = blockIdx.x;
    const int c4   = cta * 4;

    // ---- one-time weight load ----
    for (int idx = tid; idx < 4 * 1024; idx += NTHR) {
        int col = idx & 3, i = idx >> 2;
        s.wrh [col][i] = __ldg(&W_rh [(size_t)i * HS + c4 + col]);
        s.wrha[col][i] = __ldg(&W_rha[(size_t)(INSZ + i) * HS + c4 + col]);
        s.wrhm[col][i] = __ldg(&W_rhm[(size_t)(INSZ + i) * HS + c4 + col]);
    }
    for (int idx = tid; idx < 4 * 512; idx += NTHR) {
        int col = idx & 3, i = idx >> 2;
        s.wca[col][i] = __ldg(&W_ca[(size_t)i * HS + c4 + col]);
        s.wcm[col][i] = __ldg(&W_cm[(size_t)i * HS + c4 + col]);
    }
    for (int idx = tid; idx < 12 * MBK; idx += NTHR) {
        int k = idx / MBK, j = idx % MBK;
        int row = (k < 4) ? (c4 + k) : (k < 8) ? (512 + c4 + k - 4) : (1024 + c4 + k - 8);
        s.wrp_r[k][j] = __ldg(&W_rp[(size_t)row * MBK + j]);
    }
    if (tid < 36) {
        int k = tid / 3, j = tid % 3;
        int row = (k < 4) ? (c4 + k) : (k < 8) ? (512 + c4 + k - 4) : (1024 + c4 + k - 8);
        s.wwp_r[k][j] = __ldg(&W_wp[(size_t)row * 3 + j]);
    }
    for (int idx = tid; idx < 4 * MBK; idx += NTHR) {
        int k = idx / MBK, j = idx % MBK;
        s.wwpa_r[k][j] = __ldg(&W_wpa[(size_t)(c4 + k) * MBK + j]);
        s.wwpm_r[k][j] = __ldg(&W_wpm[(size_t)(c4 + k) * MBK + j]);
    }
    for (int i = tid; i < MBK; i += NTHR) s.brp_s[i] = __ldg(&b_rp[i]);
    if (tid < 3) s.bwp_s[tid] = b_wp[tid];
    if (tid < 4) s.brh[tid] = b_rh[c4 + tid];
    for (int idx = tid; idx < 4 * MBK; idx += NTHR) (&s.mem[0][0])[idx] = 0.f;
    if (tid == 0) s.epoch = 0u;
    __syncthreads();

    unsigned int barc = 0;

    for (int t = 0; t < T_STEPS; ++t) {
        const int buf  = t & 1;
        const int nbuf = buf ^ 1;

        // ============ phase A: state+logit read, softmax, c dots, r ============
        if (t == 0) {
            for (int i = tid; i < 1536; i += NTHR) s.sx[i] = 0.f;
        } else {
            for (int i = tid; i < 1536; i += NTHR) s.sx[i] = __ldcg(&g_state[i]);
        }
        if (tid < MBK) {
            s.lar [tid] = __ldcg(&g_acc[buf][tid])       + s.brp_s[tid];
            s.lawa[tid] = __ldcg(&g_acc[buf][103 + tid]) + __ldcg(&g_pre_wpa[(size_t)t * MBK + tid]);
            s.lawm[tid] = __ldcg(&g_acc[buf][203 + tid]) + __ldcg(&g_pre_wpm[(size_t)t * MBK + tid]);
        } else if (tid < MBK + 3) {
            s.law[tid - MBK] = __ldcg(&g_acc[buf][tid]) + s.bwp_s[tid - MBK];
        }
        if (tid < 4) {
            s.pre_ca [tid] = __ldcg(&g_pre_ca [(size_t)t * HS + c4 + tid]);
            s.pre_cm [tid] = __ldcg(&g_pre_cm [(size_t)t * HS + c4 + tid]);
            s.pre_rha[tid] = __ldcg(&g_pre_rha[(size_t)t * HS + c4 + tid]);
            s.pre_rhm[tid] = __ldcg(&g_pre_rhm[(size_t)t * HS + c4 + tid]);
        }
        __syncthreads();

        // warps 0-7: c_a / c_m column dots; warps 8-10: 100-wide softmaxes; warp 11: aw
        if (warp < 8) {
            int col = warp & 3;
            const float* w = (warp < 4) ? s.wca[col] : s.wcm[col];
            const float* x = (warp < 4) ? s.sx : (s.sx + 512);
            float acc = 0.f;
#pragma unroll
            for (int i = 0; i < 512; i += 32) acc = fmaf(x[i + lane], w[i + lane], acc);
            acc = warpsum(acc);
            if (lane == 0) {
                if (warp < 4) s.ca_own[col] = fmaxf(acc + s.pre_ca[col], 0.f);
                else          s.cm_own[col] = fmaxf(acc + s.pre_cm[col], 0.f);
            }
        } else if (warp < 11) {
            const float* L = (warp == 8) ? s.lar : (warp == 9) ? s.lawa : s.lawm;
            float* P       = (warp == 8) ? s.par : (warp == 9) ? s.pawa : s.pawm;
            float v[4];
#pragma unroll
            for (int k = 0; k < 4; k++) { int j = lane + 32 * k; v[k] = (j < MBK) ? L[j] : -1e30f; }
            float m = fmaxf(fmaxf(v[0], v[1]), fmaxf(v[2], v[3]));
#pragma unroll
            for (int o = 16; o; o >>= 1) m = fmaxf(m, __shfl_xor_sync(0xFFFFFFFFu, m, o));
            float e[4], sum = 0.f;
#pragma unroll
            for (int k = 0; k < 4; k++) {
                int j = lane + 32 * k;
                e[k] = (j < MBK) ? expf(v[k] - m) : 0.f;
                sum += e[k];
            }
            sum = warpsum(sum);
            float inv = 1.f / sum;
#pragma unroll
            for (int k = 0; k < 4; k++) { int j = lane + 32 * k; if (j < MBK) P[j] = e[k] * inv; }
        } else if (warp == 11 && lane == 0) {
            float l0 = s.law[0], l1 = s.law[1], l2 = s.law[2];
            float m = fmaxf(l0, fmaxf(l1, l2));
            float e0 = expf(l0 - m), e1 = expf(l1 - m), e2 = expf(l2 - m);
            float inv = 1.f / (e0 + e1 + e2);
            s.aw[0] = e0 * inv; s.aw[1] = e1 * inv; s.aw[2] = e2 * inv;
        }
        __syncthreads();

        // warps 0-3: r-dot over OLD mem
        if (warp < 4) {
            int col = warp; float acc = 0.f;
#pragma unroll
            for (int k = 0; k < 4; k++) {
                int j = lane + 32 * k;
                if (j < MBK) acc = fmaf(s.par[j], s.mem[col][j], acc);
            }
            acc = warpsum(acc);
            if (lane == 0) __stcg(&g_r[c4 + col], acc);
        }
        ++barc; gbar_arrive();

        // ---- barrier-1 shadow: x-part dots (warps 0-11, register partials)
        //      + mem update (warps 12-15) ----
        float xpart = 0.f;
        if (warp < 12) {
            int mat = warp >> 2, col = warp & 3;
            const float* w = (mat == 0) ? s.wrh[col] : (mat == 1) ? s.wrha[col] : s.wrhm[col];
            const float* x = (mat == 0) ? (s.sx + 1024) : (mat == 1) ? s.sx : (s.sx + 512);
#pragma unroll
            for (int i = lane; i < 512; i += 32) xpart = fmaf(x[i], w[512 + i], xpart);
        } else {
            float aw0 = s.aw[0], aw1 = s.aw[1], aw2 = s.aw[2];
            for (int idx = tid - 384; idx < 4 * MBK; idx += 128) {
                int col = idx & 3, j = idx >> 2;
                s.mem[col][j] = fmaf(aw0, s.mem[col][j],
                                fmaf(aw1 * s.pawa[j], s.ca_own[col],
                                     aw2 * s.pawm[j] * s.cm_own[col]));
            }
        }
        gbar_wait(barc * NCTA, &s.epoch);

        // ============ phase B: r-part dots + push next-step logits ============
        for (int i = tid; i < 512; i += NTHR) s.r[i] = __ldcg(&g_r[i]);
        // zero the just-consumed accumulator buffer (disjoint slices)
        if (warp == 14 && lane < 4 && cta < 80) __stcg(&g_acc[buf][c4 + lane], 0.f);
        __syncthreads();

        if (warp < 12) {
            int mat = warp >> 2, col = warp & 3;
            const float* w = (mat == 0) ? s.wrh[col] : (mat == 1) ? s.wrha[col] : s.wrhm[col];
            float acc = xpart;
#pragma unroll
            for (int i = lane; i < 512; i += 32) acc = fmaf(s.r[i], w[i], acc);
            acc = warpsum(acc);
            if (lane == 0) {
                if (mat == 0) {
                    float h1 = fmaxf(acc + s.brh[col], 0.f);
                    s.snew[8 + col] = h1;
                    __stcg(&g_state[1024 + c4 + col], h1);
                    out[(size_t)t * HS + c4 + col] = h1;
                } else if (mat == 1) {
                    float ha1 = fmaxf(acc + s.pre_rha[col], 0.f);
                    s.snew[col] = ha1;
                    __stcg(&g_state[c4 + col], ha1);
                } else {
                    float hm1 = fmaxf(acc + s.pre_rhm[col], 0.f);
                    s.snew[4 + col] = hm1;
                    __stcg(&g_state[512 + c4 + col], hm1);
                }
            }
        }
        __syncthreads();

        // push partial logits for step t+1 (303 spread-address float REDs)
        if (t + 1 < T_STEPS && tid < 303) {
            float p = 0.f;
            int slot;
            if (tid < MBK) {
#pragma unroll
                for (int k = 0; k < 12; k++) p = fmaf(s.snew[k], s.wrp_r[k][tid], p);
                slot = tid;
            } else if (tid < MBK + 3) {
                int j = tid - MBK;
#pragma unroll
                for (int k = 0; k < 12; k++) p = fmaf(s.snew[k], s.wwp_r[k][j], p);
                slot = 100 + j;
            } else if (tid < 203) {
                int j = tid - 103;
#pragma unroll
                for (int k = 0; k < 4; k++) p = fmaf(s.snew[k], s.wwpa_r[k][j], p);
                slot = 103 + j;
            } else {
                int j = tid - 203;
#pragma unroll
                for (int k = 0; k < 4; k++) p = fmaf(s.snew[4 + k], s.wwpm_r[k][j], p);
                slot = 203 + j;
            }
            atomicAdd(&g_acc[nbuf][slot], p);
        }
        ++barc; gbar_arrive(); gbar_wait(barc * NCTA, &s.epoch);
    }
}

// =====================================================================
extern "C" void kernel_launch(void* const* d_in, const int* in_sizes, int n_in,
                              void* d_out, int out_size)
{
    const float* Xa    = (const float*)d_in[0];
    const float* Xm    = (const float*)d_in[1];
    const float* W_ca  = (const float*)d_in[2];
    const float* b_ca  = (const float*)d_in[3];
    const float* W_cm  = (const float*)d_in[4];
    const float* b_cm  = (const float*)d_in[5];
    const float* W_wp  = (const float*)d_in[6];
    const float* b_wp  = (const float*)d_in[7];
    const float* W_wpa = (const float*)d_in[8];
    const float* b_wpa = (const float*)d_in[9];
    const float* W_wpm = (const float*)d_in[10];
    const float* b_wpm = (const float*)d_in[11];
    const float* W_rp  = (const float*)d_in[12];
    const float* b_rp  = (const float*)d_in[13];
    const float* W_rh  = (const float*)d_in[14];
    const float* b_rh  = (const float*)d_in[15];
    const float* W_rha = (const float*)d_in[16];
    const float* W_rhm = (const float*)d_in[18];
    float* out = (float*)d_out;

    static bool attr_set = false;
    if (!attr_set) {
        cudaFuncSetAttribute(seq_kernel, cudaFuncAttributeMaxDynamicSharedMemorySize,
                             (int)sizeof(SeqSmem));
        attr_set = true;
    }

    dim3 ggrid(4, T_STEPS / 128, 6);
    gemm6_kernel<<<ggrid, 256>>>(Xa, Xm,
                                 W_rha, (const float*)d_in[17],
                                 W_rhm, (const float*)d_in[19],
                                 W_ca, b_ca, W_cm, b_cm,
                                 W_wpa, b_wpa, W_wpm, b_wpm);
    reset_kernel<<<1, 512>>>();
    seq_kernel<<<NCTA, NTHR, sizeof(SeqSmem)>>>(W_ca, W_cm, W_wp, b_wp, W_wpa, W_wpm,
                                                W_rp, b_rp, W_rh, b_rh, W_rha, W_rhm,
                                                out);
}

// round 13
// speedup vs baseline: 1.2234x; 1.0485x over previous
#include <cuda_runtime.h>
#include <cuda_bf16.h>
#include <math.h>
#include <stdint.h>

#define T_STEPS 4096
#define HS 512
#define INSZ 2048
#define MBK 100
#define NCTA 128
#define NTHR 512

// ---------------- device scratch (allocations are forbidden) ----------------
__device__ float g_pre_rha[T_STEPS * HS];
__device__ float g_pre_rhm[T_STEPS * HS];
__device__ float g_pre_ca [T_STEPS * HS];
__device__ float g_pre_cm [T_STEPS * HS];
__device__ float g_pre_wpa[T_STEPS * MBK];
__device__ float g_pre_wpm[T_STEPS * MBK];
__device__ float g_state[3 * HS];          // [ha(512) | hm(512) | h(512)]
__device__ float g_r[HS];
// logit accumulators, double buffered: [0..99]=ar, [100..102]=aw,
// [103..202]=aw_a(ha part), [203..302]=aw_m(hm part)
__device__ float g_acc[2][320];
__device__ unsigned int g_bar;

__device__ __forceinline__ float warpsum(float v) {
#pragma unroll
    for (int o = 16; o; o >>= 1) v += __shfl_xor_sync(0xFFFFFFFFu, v, o);
    return v;
}

__device__ __forceinline__ unsigned int ld_acq(const unsigned int* p) {
    unsigned int v;
    asm volatile("ld.global.acquire.gpu.u32 %0, [%1];" : "=r"(v) : "l"(p));
    return v;
}

// arrive: release-atomic (with CTA-wide __syncthreads first, the release
// publishes all prior stores of the CTA at gpu scope)
__device__ __forceinline__ void gbar_arrive() {
    __syncthreads();
    if (threadIdx.x == 0)
        asm volatile("red.release.gpu.global.add.u32 [%0], 1;" :: "l"(&g_bar) : "memory");
}
// wait: warp 15 polls global with acquire, publishes epoch to SMEM; others spin SMEM.
__device__ __forceinline__ void gbar_wait(unsigned int target, volatile unsigned int* epoch) {
    const int warp = threadIdx.x >> 5, lane = threadIdx.x & 31;
    if (warp == 15) {
        if (lane == 0) {
            while (ld_acq(&g_bar) < target) {}
            *epoch = target;
        }
        __syncwarp();
    } else {
        if (lane == 0) { while (*epoch < target) {} }
        __syncwarp();
    }
}

__global__ void reset_kernel() {
    int i = blockIdx.x * blockDim.x + threadIdx.x;
    if (i == 0) g_bar = 0u;
    if (i < 2 * 320) (&g_acc[0][0])[i] = 0.f;
    if (i < 3 * HS) g_state[i] = 0.f;
    if (i < HS) g_r[i] = 0.f;
}

// =====================================================================
// Precompute GEMMs: C[4096,N] = X @ W[rowOff:+2048, :N] + bias (6 jobs in z)
// =====================================================================
__global__ __launch_bounds__(256)
void gemm6_kernel(const float* __restrict__ Xa, const float* __restrict__ Xm,
                  const float* __restrict__ W_rha, const float* __restrict__ b_rha,
                  const float* __restrict__ W_rhm, const float* __restrict__ b_rhm,
                  const float* __restrict__ W_ca,  const float* __restrict__ b_ca,
                  const float* __restrict__ W_cm,  const float* __restrict__ b_cm,
                  const float* __restrict__ W_wpa, const float* __restrict__ b_wpa,
                  const float* __restrict__ W_wpm, const float* __restrict__ b_wpm)
{
    const float* A; const float* B; const float* bias; float* C; int N; int rowOff;
    switch (blockIdx.z) {
        case 0: A = Xa; B = W_rha; bias = b_rha; C = g_pre_rha; N = HS;  rowOff = 0;   break;
        case 1: A = Xm; B = W_rhm; bias = b_rhm; C = g_pre_rhm; N = HS;  rowOff = 0;   break;
        case 2: A = Xa; B = W_ca;  bias = b_ca;  C = g_pre_ca;  N = HS;  rowOff = HS;  break;
        case 3: A = Xm; B = W_cm;  bias = b_cm;  C = g_pre_cm;  N = HS;  rowOff = HS;  break;
        case 4: A = Xa; B = W_wpa; bias = b_wpa; C = g_pre_wpa; N = MBK; rowOff = HS;  break;
        default:A = Xm; B = W_wpm; bias = b_wpm; C = g_pre_wpm; N = MBK; rowOff = HS;  break;
    }
    if ((int)blockIdx.x * 128 >= N) return;

    const int K = INSZ;
    __shared__ float As[8][128];
    __shared__ float Bs[8][128];
    const int tid  = threadIdx.x;
    const int tx   = tid & 15, ty = tid >> 4;
    const int brow = blockIdx.y, bcol = blockIdx.x;

    const int arow = tid >> 1, akq = (tid & 1) * 4;
    const float* Ag = A + (size_t)(brow * 128 + arow) * K + akq;
    const int bk = tid >> 5, bc = (tid & 31) * 4;
    const int gcol = bcol * 128 + bc;
    const bool bok = (gcol + 3 < N);

    float acc[8][8];
#pragma unroll
    for (int i = 0; i < 8; i++)
#pragma unroll
        for (int j = 0; j < 8; j++) acc[i][j] = 0.f;

    for (int k0 = 0; k0 < K; k0 += 8) {
        float4 av = *(const float4*)(Ag + k0);
        As[akq + 0][arow] = av.x; As[akq + 1][arow] = av.y;
        As[akq + 2][arow] = av.z; As[akq + 3][arow] = av.w;
        float4 bv = bok ? *(const float4*)(B + (size_t)(rowOff + k0 + bk) * N + gcol)
                        : make_float4(0.f, 0.f, 0.f, 0.f);
        *(float4*)&Bs[bk][bc] = bv;
        __syncthreads();
#pragma unroll
        for (int kk = 0; kk < 8; ++kk) {
            float ra[8], rb[8];
            *(float4*)(ra)     = *(const float4*)&As[kk][ty * 4];
            *(float4*)(ra + 4) = *(const float4*)&As[kk][64 + ty * 4];
            *(float4*)(rb)     = *(const float4*)&Bs[kk][tx * 4];
            *(float4*)(rb + 4) = *(const float4*)&Bs[kk][64 + tx * 4];
#pragma unroll
            for (int i = 0; i < 8; i++)
#pragma unroll
                for (int j = 0; j < 8; j++) acc[i][j] = fmaf(ra[i], rb[j], acc[i][j]);
        }
        __syncthreads();
    }
#pragma unroll
    for (int i = 0; i < 8; i++) {
        int row = brow * 128 + ((i < 4) ? (ty * 4 + i) : (64 + ty * 4 + i - 4));
#pragma unroll
        for (int j = 0; j < 8; j++) {
            int col = bcol * 128 + ((j < 4) ? (tx * 4 + j) : (64 + tx * 4 + j - 4));
            if (col < N) C[(size_t)row * N + col] = acc[i][j] + bias[col];
        }
    }
}

// =====================================================================
// Persistent sequential kernel: 128 CTAs x 512 threads, each owns 4 HS columns.
// 2 global rounds per step; direct global reads (no staging syncs).
// =====================================================================
struct SeqSmem {
    float wrh [4][1024];   // W_rh  col slices: rows [r(512) | h(512)]
    float wrha[4][1024];   // W_rha rows 2048..3071: [r | ha]
    float wrhm[4][1024];   // W_rhm rows 2048..3071: [r | hm]
    float wca [4][512];    // W_ca rows 0..511 (ha)
    float wcm [4][512];    // W_cm rows 0..511 (hm)
    float wrp_r [12][104]; // W_rp rows owned x 100 logits
    float wwp_r [12][4];   // W_wp rows owned x 3
    float wwpa_r[4][104];  // W_wpa rows c4..+3 (ha part) x 100
    float wwpm_r[4][104];
    float mem [4][MBK];    // mem[:, owned cols], col-major
    float sx  [1536];      // state staged for x-part dots (shadow use)
    float par [MBK], pawa[MBK], pawm[MBK], aw[3];
    float snew[12];        // new state own comps: [ha1(4) | hm1(4) | h1(4)]
    float ca_own[4], cm_own[4];
    float pre_rha[4], pre_rhm[4];
    float brh[4];
    float brp_s[MBK], bwp_s[3];
    unsigned int epoch;
};

__global__ __launch_bounds__(NTHR, 1)
void seq_kernel(const float* __restrict__ W_ca,  const float* __restrict__ W_cm,
                const float* __restrict__ W_wp,  const float* __restrict__ b_wp,
                const float* __restrict__ W_wpa, const float* __restrict__ W_wpm,
                const float* __restrict__ W_rp,  const float* __restrict__ b_rp,
                const float* __restrict__ W_rh,  const float* __restrict__ b_rh,
                const float* __restrict__ W_rha, const float* __restrict__ W_rhm,
                float* __restrict__ out)
{
    extern __shared__ float smem_raw[];
    SeqSmem& s = *reinterpret_cast<SeqSmem*>(smem_raw);
    const int tid  = threadIdx.x;
    const int warp = tid >> 5, lane = tid & 31;
    const int cta  = blockIdx.x;
    const int c4   = cta * 4;

    // ---- one-time weight load ----
    for (int idx = tid; idx < 4 * 1024; idx += NTHR) {
        int col = idx & 3, i = idx >> 2;
        s.wrh [col][i] = __ldg(&W_rh [(size_t)i * HS + c4 + col]);
        s.wrha[col][i] = __ldg(&W_rha[(size_t)(INSZ + i) * HS + c4 + col]);
        s.wrhm[col][i] = __ldg(&W_rhm[(size_t)(INSZ + i) * HS + c4 + col]);
    }
    for (int idx = tid; idx < 4 * 512; idx += NTHR) {
        int col = idx & 3, i = idx >> 2;
        s.wca[col][i] = __ldg(&W_ca[(size_t)i * HS + c4 + col]);
        s.wcm[col][i] = __ldg(&W_cm[(size_t)i * HS + c4 + col]);
    }
    for (int idx = tid; idx < 12 * MBK; idx += NTHR) {
        int k = idx / MBK, j = idx % MBK;
        int row = (k < 4) ? (c4 + k) : (k < 8) ? (512 + c4 + k - 4) : (1024 + c4 + k - 8);
        s.wrp_r[k][j] = __ldg(&W_rp[(size_t)row * MBK + j]);
    }
    if (tid < 36) {
        int k = tid / 3, j = tid % 3;
        int row = (k < 4) ? (c4 + k) : (k < 8) ? (512 + c4 + k - 4) : (1024 + c4 + k - 8);
        s.wwp_r[k][j] = __ldg(&W_wp[(size_t)row * 3 + j]);
    }
    for (int idx = tid; idx < 4 * MBK; idx += NTHR) {
        int k = idx / MBK, j = idx % MBK;
        s.wwpa_r[k][j] = __ldg(&W_wpa[(size_t)(c4 + k) * MBK + j]);
        s.wwpm_r[k][j] = __ldg(&W_wpm[(size_t)(c4 + k) * MBK + j]);
    }
    for (int i = tid; i < MBK; i += NTHR) s.brp_s[i] = __ldg(&b_rp[i]);
    if (tid < 3) s.bwp_s[tid] = b_wp[tid];
    if (tid < 4) s.brh[tid] = b_rh[c4 + tid];
    for (int idx = tid; idx < 4 * MBK; idx += NTHR) (&s.mem[0][0])[idx] = 0.f;
    if (tid == 0) s.epoch = 0u;
    __syncthreads();

    unsigned int barc = 0;

    for (int t = 0; t < T_STEPS; ++t) {
        const int buf  = t & 1;
        const int nbuf = buf ^ 1;

        // ============ phase A (no staging sync; direct global reads) ============
        if (warp < 8) {
            // c_a (warps 0-3) / c_m (warps 4-7): direct g_state reads
            int col = warp & 3;
            bool isA = warp < 4;
            float pre = 0.f;
            if (lane == 0)
                pre = __ldcg(isA ? &g_pre_ca[(size_t)t * HS + c4 + col]
                                 : &g_pre_cm[(size_t)t * HS + c4 + col]);
            const float* w  = isA ? s.wca[col] : s.wcm[col];
            const float* xg = isA ? g_state : (g_state + 512);
            float acc = 0.f;
#pragma unroll
            for (int i = 0; i < 512; i += 32) acc = fmaf(__ldcg(&xg[i + lane]), w[i + lane], acc);
            acc = warpsum(acc);
            if (lane == 0) {
                if (isA) s.ca_own[col] = fmaxf(acc + pre, 0.f);
                else     s.cm_own[col] = fmaxf(acc + pre, 0.f);
            }
        } else if (warp < 11) {
            // softmaxes with direct logit loads
            float v[4];
#pragma unroll
            for (int k = 0; k < 4; k++) {
                int j = lane + 32 * k;
                if (j < MBK) {
                    if (warp == 8)      v[k] = __ldcg(&g_acc[buf][j]) + s.brp_s[j];
                    else if (warp == 9) v[k] = __ldcg(&g_acc[buf][103 + j]) + __ldcg(&g_pre_wpa[(size_t)t * MBK + j]);
                    else                v[k] = __ldcg(&g_acc[buf][203 + j]) + __ldcg(&g_pre_wpm[(size_t)t * MBK + j]);
                } else v[k] = -1e30f;
            }
            float m = fmaxf(fmaxf(v[0], v[1]), fmaxf(v[2], v[3]));
#pragma unroll
            for (int o = 16; o; o >>= 1) m = fmaxf(m, __shfl_xor_sync(0xFFFFFFFFu, m, o));
            float e[4], sum = 0.f;
#pragma unroll
            for (int k = 0; k < 4; k++) {
                int j = lane + 32 * k;
                e[k] = (j < MBK) ? expf(v[k] - m) : 0.f;
                sum += e[k];
            }
            sum = warpsum(sum);
            float inv = 1.f / sum;
            float* P = (warp == 8) ? s.par : (warp == 9) ? s.pawa : s.pawm;
#pragma unroll
            for (int k = 0; k < 4; k++) { int j = lane + 32 * k; if (j < MBK) P[j] = e[k] * inv; }
        } else if (warp == 11) {
            if (lane == 0) {
                float l0 = __ldcg(&g_acc[buf][100]) + s.bwp_s[0];
                float l1 = __ldcg(&g_acc[buf][101]) + s.bwp_s[1];
                float l2 = __ldcg(&g_acc[buf][102]) + s.bwp_s[2];
                float m = fmaxf(l0, fmaxf(l1, l2));
                float e0 = expf(l0 - m), e1 = expf(l1 - m), e2 = expf(l2 - m);
                float inv = 1.f / (e0 + e1 + e2);
                s.aw[0] = e0 * inv; s.aw[1] = e1 * inv; s.aw[2] = e2 * inv;
            }
        } else {
            // warps 12-15: stage sx for the shadow x-part dots
            for (int i = tid - 384; i < 1536; i += 128) s.sx[i] = __ldcg(&g_state[i]);
            if (warp == 12 && lane < 8) {
                int k = lane & 3;
                if (lane < 4) s.pre_rha[k] = __ldcg(&g_pre_rha[(size_t)t * HS + c4 + k]);
                else          s.pre_rhm[k] = __ldcg(&g_pre_rhm[(size_t)t * HS + c4 + k]);
            }
        }
        __syncthreads();

        // warps 0-3: r-dot over OLD mem
        if (warp < 4) {
            int col = warp; float acc = 0.f;
#pragma unroll
            for (int k = 0; k < 4; k++) {
                int j = lane + 32 * k;
                if (j < MBK) acc = fmaf(s.par[j], s.mem[col][j], acc);
            }
            acc = warpsum(acc);
            if (lane == 0) __stcg(&g_r[c4 + col], acc);
        }
        ++barc; gbar_arrive();

        // ---- barrier-1 shadow: x-part dots (warps 0-11) + mem update (12-15) ----
        float xpart = 0.f;
        if (warp < 12) {
            int mat = warp >> 2, col = warp & 3;
            const float* w = (mat == 0) ? s.wrh[col] : (mat == 1) ? s.wrha[col] : s.wrhm[col];
            const float* x = (mat == 0) ? (s.sx + 1024) : (mat == 1) ? s.sx : (s.sx + 512);
#pragma unroll
            for (int i = lane; i < 512; i += 32) xpart = fmaf(x[i], w[512 + i], xpart);
        } else {
            float aw0 = s.aw[0], aw1 = s.aw[1], aw2 = s.aw[2];
            for (int idx = tid - 384; idx < 4 * MBK; idx += 128) {
                int col = idx & 3, j = idx >> 2;
                s.mem[col][j] = fmaf(aw0, s.mem[col][j],
                                fmaf(aw1 * s.pawa[j], s.ca_own[col],
                                     aw2 * s.pawm[j] * s.cm_own[col]));
            }
        }
        gbar_wait(barc * NCTA, &s.epoch);

        // ============ phase B: r-part dots (direct g_r reads) + logit push ============
        if (warp == 14 && lane < 4 && cta < 80) __stcg(&g_acc[buf][c4 + lane], 0.f);
        if (warp < 12) {
            int mat = warp >> 2, col = warp & 3;
            const float* w = (mat == 0) ? s.wrh[col] : (mat == 1) ? s.wrha[col] : s.wrhm[col];
            float acc = xpart;
#pragma unroll
            for (int i = lane; i < 512; i += 32) acc = fmaf(__ldcg(&g_r[i]), w[i], acc);
            acc = warpsum(acc);
            if (lane == 0) {
                if (mat == 0) {
                    float h1 = fmaxf(acc + s.brh[col], 0.f);
                    s.snew[8 + col] = h1;
                    __stcg(&g_state[1024 + c4 + col], h1);
                    out[(size_t)t * HS + c4 + col] = h1;
                } else if (mat == 1) {
                    float ha1 = fmaxf(acc + s.pre_rha[col], 0.f);
                    s.snew[col] = ha1;
                    __stcg(&g_state[c4 + col], ha1);
                } else {
                    float hm1 = fmaxf(acc + s.pre_rhm[col], 0.f);
                    s.snew[4 + col] = hm1;
                    __stcg(&g_state[512 + c4 + col], hm1);
                }
            }
        }
        __syncthreads();

        // push partial logits for step t+1 (303 spread-address float REDs)
        if (t + 1 < T_STEPS && tid < 303) {
            float p = 0.f;
            int slot;
            if (tid < MBK) {
#pragma unroll
                for (int k = 0; k < 12; k++) p = fmaf(s.snew[k], s.wrp_r[k][tid], p);
                slot = tid;
            } else if (tid < MBK + 3) {
                int j = tid - MBK;
#pragma unroll
                for (int k = 0; k < 12; k++) p = fmaf(s.snew[k], s.wwp_r[k][j], p);
                slot = 100 + j;
            } else if (tid < 203) {
                int j = tid - 103;
#pragma unroll
                for (int k = 0; k < 4; k++) p = fmaf(s.snew[k], s.wwpa_r[k][j], p);
                slot = 103 + j;
            } else {
                int j = tid - 203;
#pragma unroll
                for (int k = 0; k < 4; k++) p = fmaf(s.snew[4 + k], s.wwpm_r[k][j], p);
                slot = 203 + j;
            }
            atomicAdd(&g_acc[nbuf][slot], p);
        }
        ++barc; gbar_arrive(); gbar_wait(barc * NCTA, &s.epoch);
    }
}

// =====================================================================
extern "C" void kernel_launch(void* const* d_in, const int* in_sizes, int n_in,
                              void* d_out, int out_size)
{
    const float* Xa    = (const float*)d_in[0];
    const float* Xm    = (const float*)d_in[1];
    const float* W_ca  = (const float*)d_in[2];
    const float* b_ca  = (const float*)d_in[3];
    const float* W_cm  = (const float*)d_in[4];
    const float* b_cm  = (const float*)d_in[5];
    const float* W_wp  = (const float*)d_in[6];
    const float* b_wp  = (const float*)d_in[7];
    const float* W_wpa = (const float*)d_in[8];
    const float* b_wpa = (const float*)d_in[9];
    const float* W_wpm = (const float*)d_in[10];
    const float* b_wpm = (const float*)d_in[11];
    const float* W_rp  = (const float*)d_in[12];
    const float* b_rp  = (const float*)d_in[13];
    const float* W_rh  = (const float*)d_in[14];
    const float* b_rh  = (const float*)d_in[15];
    const float* W_rha = (const float*)d_in[16];
    const float* W_rhm = (const float*)d_in[18];
    float* out = (float*)d_out;

    static bool attr_set = false;
    if (!attr_set) {
        cudaFuncSetAttribute(seq_kernel, cudaFuncAttributeMaxDynamicSharedMemorySize,
                             (int)sizeof(SeqSmem));
        attr_set = true;
    }

    dim3 ggrid(4, T_STEPS / 128, 6);
    gemm6_kernel<<<ggrid, 256>>>(Xa, Xm,
                                 W_rha, (const float*)d_in[17],
                                 W_rhm, (const float*)d_in[19],
                                 W_ca, b_ca, W_cm, b_cm,
                                 W_wpa, b_wpa, W_wpm, b_wpm);
    reset_kernel<<<4, 512>>>();
    seq_kernel<<<NCTA, NTHR, sizeof(SeqSmem)>>>(W_ca, W_cm, W_wp, b_wp, W_wpa, W_wpm,
                                                W_rp, b_rp, W_rh, b_rh, W_rha, W_rhm,
                                                out);
}